// round 1
// baseline (speedup 1.0000x reference)
#include <cuda_runtime.h>
#include <math.h>

#define BB 8
#define SEQ 4096
#define DM 1024
#define NS 64
#define SCH 64   // scan steps per smem chunk

// ---------------- static scratch (no allocations allowed) ----------------
__device__ float g_Bs[NS * DM];            // sigmoid(B_w), [N, D]
__device__ float g_Aperm[DM * NS];         // sigmoid(A_raw), permuted n
__device__ float g_Cperm[DM * NS];         // sigmoid(C_w), permuted n
__device__ float g_g[DM];                  // sigmoid(gamma)
__device__ float g_U[(size_t)BB * SEQ * NS]; // X @ Bm^T, permuted n

__device__ __forceinline__ float sigmoidf_(float v) {
    return 1.0f / (1.0f + expf(-v));
}

// fma with saturate-to-[0,1] in one instruction: clip(h*A + inp, 0, 1)
__device__ __forceinline__ float fmasat(float a, float b, float c) {
    float r;
    asm("fma.rn.sat.f32 %0, %1, %2, %3;" : "=f"(r) : "f"(a), "f"(b), "f"(c));
    return r;
}

// permutation: state n -> storage position p, so that lane lp=n%8 reads
// its 8 states (n = lp + 8j) from 8 contiguous floats (2x LDS.128)
__device__ __forceinline__ int permn(int n) { return ((n & 7) << 3) | (n >> 3); }

// ---------------- kernel 1: precompute sigmoids ----------------
__global__ void prep_kernel(const float* __restrict__ A_raw,
                            const float* __restrict__ B_w,
                            const float* __restrict__ C_w,
                            const float* __restrict__ gamma) {
    int i = blockIdx.x * 256 + threadIdx.x;
    if (i < NS * DM) {
        g_Bs[i] = sigmoidf_(B_w[i]);           // B_w is [N, D]
        int d = i >> 6, n = i & 63;            // A_raw / C_w are [D, N]
        int p = permn(n);
        g_Aperm[(d << 6) + p] = sigmoidf_(A_raw[i]);
        g_Cperm[(d << 6) + p] = sigmoidf_(C_w[i]);
    }
    if (i < DM) g_g[i] = sigmoidf_(gamma[i]);
}

// ---------------- kernel 2: U = X @ Bs^T  ([32768,1024] x [64,1024]^T) ----
__global__ void __launch_bounds__(256) gemm_kernel(const float* __restrict__ X) {
    __shared__ float Xs[32][68];  // k-major, padded (272B row stride, 16B aligned)
    __shared__ float Ws[32][68];
    int tid = threadIdx.x;
    int row0 = blockIdx.x * 64;
    int tx = tid & 15, ty = tid >> 4;
    float acc[4][4];
#pragma unroll
    for (int i = 0; i < 4; i++)
#pragma unroll
        for (int j = 0; j < 4; j++) acc[i][j] = 0.0f;

    for (int k0 = 0; k0 < DM; k0 += 32) {
        __syncthreads();
#pragma unroll
        for (int i = tid; i < 512; i += 256) {   // 512 float4 = 2048 floats per tile
            int r = i >> 3, q = i & 7;
            float4 v = *(const float4*)(X + (size_t)(row0 + r) * DM + k0 + q * 4);
            Xs[q * 4 + 0][r] = v.x; Xs[q * 4 + 1][r] = v.y;
            Xs[q * 4 + 2][r] = v.z; Xs[q * 4 + 3][r] = v.w;
            float4 w = *(const float4*)(g_Bs + (size_t)r * DM + k0 + q * 4);
            Ws[q * 4 + 0][r] = w.x; Ws[q * 4 + 1][r] = w.y;
            Ws[q * 4 + 2][r] = w.z; Ws[q * 4 + 3][r] = w.w;
        }
        __syncthreads();
#pragma unroll
        for (int k = 0; k < 32; k++) {
            float4 xa = *(const float4*)&Xs[k][ty * 4];
            float4 wb = *(const float4*)&Ws[k][tx * 4];
            float xr[4] = {xa.x, xa.y, xa.z, xa.w};
            float wr[4] = {wb.x, wb.y, wb.z, wb.w};
#pragma unroll
            for (int i = 0; i < 4; i++)
#pragma unroll
                for (int j = 0; j < 4; j++) acc[i][j] = fmaf(xr[i], wr[j], acc[i][j]);
        }
    }
#pragma unroll
    for (int i = 0; i < 4; i++)
#pragma unroll
        for (int j = 0; j < 4; j++) {
            int n = tx * 4 + j;
            g_U[(size_t)(row0 + ty * 4 + i) * NS + permn(n)] = acc[i][j];
        }
}

// ---------------- kernel 3: sequential scan ----------------
// grid (D/16, B), block 128. Warp owns 4 d's (8 lanes each), lane owns 8 n-states.
__global__ void __launch_bounds__(128) scan_kernel(const float* __restrict__ X,
                                                   float* __restrict__ Y,
                                                   float* __restrict__ Hout) {
    __shared__ float us[SCH * 64];   // u chunk, permuted-n layout
    __shared__ float xs[SCH * 16];   // x chunk for this CTA's 16 d
    __shared__ float ys[SCH * 16];   // y chunk (pre-normalization)

    int b = blockIdx.y;
    int dbase = blockIdx.x << 4;
    int tid = threadIdx.x;
    int warp = tid >> 5, lane = tid & 31;
    int grp = lane >> 3, lp = lane & 7;
    int dloc = (warp << 2) | grp;    // 0..15
    int d = dbase + dloc;

    float A0[8], C0[8], h[8];
    {
        const float4* ap = (const float4*)(g_Aperm + ((size_t)d << 6) + (lp << 3));
        float4 a0 = ap[0], a1 = ap[1];
        A0[0] = a0.x; A0[1] = a0.y; A0[2] = a0.z; A0[3] = a0.w;
        A0[4] = a1.x; A0[5] = a1.y; A0[6] = a1.z; A0[7] = a1.w;
        const float4* cp = (const float4*)(g_Cperm + ((size_t)d << 6) + (lp << 3));
        float4 c0 = cp[0], c1 = cp[1];
        C0[0] = c0.x; C0[1] = c0.y; C0[2] = c0.z; C0[3] = c0.w;
        C0[4] = c1.x; C0[5] = c1.y; C0[6] = c1.z; C0[7] = c1.w;
    }
#pragma unroll
    for (int j = 0; j < 8; j++) h[j] = 0.0f;

    const size_t xbase = (size_t)b * SEQ * DM;

    for (int s0 = 0; s0 < SEQ; s0 += SCH) {
        __syncthreads();
        {   // stage u chunk (coalesced, contiguous)
            const float4* src = (const float4*)(g_U + ((size_t)b * SEQ + s0) * NS);
            float4* dst = (float4*)us;
#pragma unroll
            for (int i = 0; i < 8; i++) dst[tid + (i << 7)] = src[tid + (i << 7)];
            // stage x chunk: SCH rows x 16 d
#pragma unroll
            for (int i = 0; i < 2; i++) {
                int idx = tid + (i << 7);
                int sl = idx >> 2, q = idx & 3;
                ((float4*)xs)[idx] =
                    *(const float4*)(X + xbase + (size_t)(s0 + sl) * DM + dbase + (q << 2));
            }
        }
        __syncthreads();

#pragma unroll 8
        for (int sl = 0; sl < SCH; ++sl) {
            const float* up = us + (sl << 6) + (lp << 3);
            float4 u0 = *(const float4*)up;
            float4 u1 = *(const float4*)(up + 4);
            float xv = xs[(sl << 4) + dloc];
            h[0] = fmasat(h[0], A0[0], u0.x * xv);
            h[1] = fmasat(h[1], A0[1], u0.y * xv);
            h[2] = fmasat(h[2], A0[2], u0.z * xv);
            h[3] = fmasat(h[3], A0[3], u0.w * xv);
            h[4] = fmasat(h[4], A0[4], u1.x * xv);
            h[5] = fmasat(h[5], A0[5], u1.y * xv);
            h[6] = fmasat(h[6], A0[6], u1.z * xv);
            h[7] = fmasat(h[7], A0[7], u1.w * xv);
            float p0 = h[0] * C0[0];
            float p1 = h[1] * C0[1];
            p0 = fmaf(h[2], C0[2], p0); p1 = fmaf(h[3], C0[3], p1);
            p0 = fmaf(h[4], C0[4], p0); p1 = fmaf(h[5], C0[5], p1);
            p0 = fmaf(h[6], C0[6], p0); p1 = fmaf(h[7], C0[7], p1);
            float p = p0 + p1;
            p += __shfl_xor_sync(0xffffffffu, p, 1, 8);
            p += __shfl_xor_sync(0xffffffffu, p, 2, 8);
            p += __shfl_xor_sync(0xffffffffu, p, 4, 8);
            if (lp == 0) ys[(sl << 4) + dloc] = p;
        }
        __syncthreads();
        // dump y chunk (coalesced) into d_out's y region
#pragma unroll
        for (int i = 0; i < 2; i++) {
            int idx = tid + (i << 7);
            int sl = idx >> 2, q = idx & 3;
            *(float4*)(Y + ((size_t)b * SEQ + s0 + sl) * DM + dbase + (q << 2)) =
                ((float4*)ys)[idx];
        }
    }

    if (Hout) {   // h_final [B, D, N], n = lp + 8j
#pragma unroll
        for (int j = 0; j < 8; j++)
            Hout[(((size_t)b * DM + d) << 6) + lp + (j << 3)] = h[j];
    }
}

// ---------------- kernel 4: normalize + residual + clip (in place) -------
__global__ void __launch_bounds__(256) finalize_kernel(const float* __restrict__ X,
                                                       float* __restrict__ out) {
    size_t row = blockIdx.x;   // b*SEQ + s
    int tid = threadIdx.x;
    float4 v = ((const float4*)(out + row * DM))[tid];
    float ps = v.x + v.y + v.z + v.w;
#pragma unroll
    for (int o = 16; o; o >>= 1) ps += __shfl_xor_sync(0xffffffffu, ps, o);
    __shared__ float wsum[8];
    if ((tid & 31) == 0) wsum[tid >> 5] = ps;
    __syncthreads();
    float tot = 0.0f;
#pragma unroll
    for (int w = 0; w < 8; w++) tot += wsum[w];
    float inv = 1.0f / (tot + 1e-6f);
    float4 xv = ((const float4*)(X + row * DM))[tid];
    float4 gv = ((const float4*)g_g)[tid];
    float4 r;
    r.x = __saturatef(fmaf(v.x * gv.x, inv, xv.x));
    r.y = __saturatef(fmaf(v.y * gv.y, inv, xv.y));
    r.z = __saturatef(fmaf(v.z * gv.z, inv, xv.z));
    r.w = __saturatef(fmaf(v.w * gv.w, inv, xv.w));
    ((float4*)(out + row * DM))[tid] = r;
}

// ---------------- launch ----------------
extern "C" void kernel_launch(void* const* d_in, const int* in_sizes, int n_in,
                              void* d_out, int out_size) {
    const float* x     = (const float*)d_in[0];
    const float* A_raw = (const float*)d_in[1];
    const float* B_w   = (const float*)d_in[2];
    const float* C_w   = (const float*)d_in[3];
    const float* gamma = (const float*)d_in[4];
    float* out = (float*)d_out;

    const size_t Y_ELEMS = (size_t)BB * SEQ * DM;       // 33,554,432
    const size_t H_ELEMS = (size_t)BB * DM * NS;        // 524,288
    float* hout = ((size_t)out_size >= Y_ELEMS + H_ELEMS) ? (out + Y_ELEMS) : nullptr;

    prep_kernel<<<256, 256>>>(A_raw, B_w, C_w, gamma);
    gemm_kernel<<<(BB * SEQ) / 64, 256>>>(x);
    scan_kernel<<<dim3(DM / 16, BB), 128>>>(x, out, hout);
    finalize_kernel<<<BB * SEQ, 256>>>(x, out);
}

// round 6
// speedup vs baseline: 1.1603x; 1.1603x over previous
#include <cuda_runtime.h>
#include <math.h>

#define BB 8
#define SEQ 4096
#define DM 1024
#define NS 64
#define SCH 64          // scan steps per smem chunk
#define CHUNK 512       // sequence chunk per CTA (parallel-in-time)
#define WARM 64         // warmup steps (state error <= 0.7311^64 ~ 2e-9)
#define NCHUNK (SEQ / CHUNK)

// ---------------- static scratch (no allocations allowed) ----------------
__device__ float g_Bs[NS * DM];              // sigmoid(B_w), [N, D]
__device__ float g_Aperm[DM * NS];           // sigmoid(A_raw), permuted n
__device__ float g_Cperm[DM * NS];           // sigmoid(C_w), permuted n
__device__ float g_g[DM];                    // sigmoid(gamma)
__device__ float g_U[(size_t)BB * SEQ * NS]; // X @ Bm^T, permuted n

__device__ __forceinline__ float sigmoidf_(float v) {
    return 1.0f / (1.0f + expf(-v));
}

// fma with saturate-to-[0,1] in one instruction: clip(h*A + inp, 0, 1)
__device__ __forceinline__ float fmasat(float a, float b, float c) {
    float r;
    asm("fma.rn.sat.f32 %0, %1, %2, %3;" : "=f"(r) : "f"(a), "f"(b), "f"(c));
    return r;
}

// permutation: state n -> storage position, lane lp=n%4 owns n = lp + 4j,
// stored at lp*16 + j so each lane reads 16 contiguous floats (4x LDS.128)
__device__ __forceinline__ int permn(int n) { return ((n & 3) << 4) | (n >> 2); }

// ---------------- kernel 1: precompute sigmoids ----------------
__global__ void prep_kernel(const float* __restrict__ A_raw,
                            const float* __restrict__ B_w,
                            const float* __restrict__ C_w,
                            const float* __restrict__ gamma) {
    int i = blockIdx.x * 256 + threadIdx.x;
    if (i < NS * DM) {
        g_Bs[i] = sigmoidf_(B_w[i]);           // B_w is [N, D]
        int d = i >> 6, n = i & 63;            // A_raw / C_w are [D, N]
        int p = permn(n);
        g_Aperm[(d << 6) + p] = sigmoidf_(A_raw[i]);
        g_Cperm[(d << 6) + p] = sigmoidf_(C_w[i]);
    }
    if (i < DM) g_g[i] = sigmoidf_(gamma[i]);
}

// ---------------- kernel 2: U = X @ Bs^T  ([32768,1024] x [64,1024]^T) ----
__global__ void __launch_bounds__(256) gemm_kernel(const float* __restrict__ X) {
    __shared__ float Xs[32][68];  // k-major, padded
    __shared__ float Ws[32][68];
    int tid = threadIdx.x;
    int row0 = blockIdx.x * 64;
    int tx = tid & 15, ty = tid >> 4;
    float acc[4][4];
#pragma unroll
    for (int i = 0; i < 4; i++)
#pragma unroll
        for (int j = 0; j < 4; j++) acc[i][j] = 0.0f;

    for (int k0 = 0; k0 < DM; k0 += 32) {
        __syncthreads();
#pragma unroll
        for (int i = tid; i < 512; i += 256) {
            int r = i >> 3, q = i & 7;
            float4 v = *(const float4*)(X + (size_t)(row0 + r) * DM + k0 + q * 4);
            Xs[q * 4 + 0][r] = v.x; Xs[q * 4 + 1][r] = v.y;
            Xs[q * 4 + 2][r] = v.z; Xs[q * 4 + 3][r] = v.w;
            float4 w = *(const float4*)(g_Bs + (size_t)r * DM + k0 + q * 4);
            Ws[q * 4 + 0][r] = w.x; Ws[q * 4 + 1][r] = w.y;
            Ws[q * 4 + 2][r] = w.z; Ws[q * 4 + 3][r] = w.w;
        }
        __syncthreads();
#pragma unroll
        for (int k = 0; k < 32; k++) {
            float4 xa = *(const float4*)&Xs[k][ty * 4];
            float4 wb = *(const float4*)&Ws[k][tx * 4];
            float xr[4] = {xa.x, xa.y, xa.z, xa.w};
            float wr[4] = {wb.x, wb.y, wb.z, wb.w};
#pragma unroll
            for (int i = 0; i < 4; i++)
#pragma unroll
                for (int j = 0; j < 4; j++) acc[i][j] = fmaf(xr[i], wr[j], acc[i][j]);
        }
    }
#pragma unroll
    for (int i = 0; i < 4; i++)
#pragma unroll
        for (int j = 0; j < 4; j++) {
            int n = tx * 4 + j;
            g_U[(size_t)(row0 + ty * 4 + i) * NS + permn(n)] = acc[i][j];
        }
}

// ---------------- kernel 3: chunked parallel scan ----------------
// grid (D/32, NCHUNK, B), block 128. Warp owns 8 d's (4 lanes each),
// lane owns 16 n-states. Chunks overlap 64 warmup steps (contraction
// factor <= sigmoid(1)^64 ~ 2e-9 kills initial-state error).

template <bool WRITE_Y>
__device__ __forceinline__ void scan_chunk(
    const float* __restrict__ us, const float* __restrict__ xs,
    float* __restrict__ ys, float* h, const float* A0, const float* C0,
    int lp, int dloc) {
#pragma unroll 2
    for (int sl = 0; sl < SCH; ++sl) {
        const float* up = us + (sl << 6) + (lp << 4);
        float4 u0 = *(const float4*)(up);
        float4 u1 = *(const float4*)(up + 4);
        float4 u2 = *(const float4*)(up + 8);
        float4 u3 = *(const float4*)(up + 12);
        float xv = xs[(sl << 5) + dloc];
        float uu[16] = {u0.x, u0.y, u0.z, u0.w, u1.x, u1.y, u1.z, u1.w,
                        u2.x, u2.y, u2.z, u2.w, u3.x, u3.y, u3.z, u3.w};
#pragma unroll
        for (int j = 0; j < 16; j++) h[j] = fmasat(h[j], A0[j], uu[j] * xv);
        if (WRITE_Y) {
            float p0 = h[0] * C0[0], p1 = h[1] * C0[1];
#pragma unroll
            for (int j = 2; j < 16; j += 2) {
                p0 = fmaf(h[j], C0[j], p0);
                p1 = fmaf(h[j + 1], C0[j + 1], p1);
            }
            float p = p0 + p1;
            p += __shfl_xor_sync(0xffffffffu, p, 1, 4);
            p += __shfl_xor_sync(0xffffffffu, p, 2, 4);
            if (lp == 0) ys[(sl << 5) + dloc] = p;
        }
    }
}

__global__ void __launch_bounds__(128) scan_kernel(const float* __restrict__ X,
                                                   float* __restrict__ Y,
                                                   float* __restrict__ Hout) {
    __shared__ float us[SCH * 64];   // u chunk, permuted-n layout
    __shared__ float xs[SCH * 32];   // x chunk for this CTA's 32 d
    __shared__ float ys[SCH * 32];   // y chunk (pre-normalization)

    int b = blockIdx.z;
    int c = blockIdx.y;
    int dbase = blockIdx.x << 5;
    int tid = threadIdx.x;
    int warp = tid >> 5, lane = tid & 31;
    int grp = lane >> 2, lp = lane & 3;
    int dloc = (warp << 3) | grp;    // 0..31
    int d = dbase + dloc;

    float A0[16], C0[16], h[16];
#pragma unroll
    for (int q = 0; q < 4; q++) {
        float4 a = ((const float4*)(g_Aperm + ((size_t)d << 6) + (lp << 4)))[q];
        A0[q * 4 + 0] = a.x; A0[q * 4 + 1] = a.y; A0[q * 4 + 2] = a.z; A0[q * 4 + 3] = a.w;
        float4 cc = ((const float4*)(g_Cperm + ((size_t)d << 6) + (lp << 4)))[q];
        C0[q * 4 + 0] = cc.x; C0[q * 4 + 1] = cc.y; C0[q * 4 + 2] = cc.z; C0[q * 4 + 3] = cc.w;
    }
#pragma unroll
    for (int j = 0; j < 16; j++) h[j] = 0.0f;

    const size_t xbase = (size_t)b * SEQ * DM;
    const int s_out0 = c * CHUNK;
    const int s_begin = (c == 0) ? 0 : s_out0 - WARM;
    const int s_end = s_out0 + CHUNK;

    for (int s0 = s_begin; s0 < s_end; s0 += SCH) {
        __syncthreads();
        {   // stage u chunk (coalesced, contiguous): 64 steps x 64 floats
            const float4* src = (const float4*)(g_U + ((size_t)b * SEQ + s0) * NS);
            float4* dst = (float4*)us;
#pragma unroll
            for (int i = 0; i < 8; i++) dst[tid + (i << 7)] = src[tid + (i << 7)];
            // stage x chunk: 64 steps x 32 d
#pragma unroll
            for (int i = 0; i < 4; i++) {
                int idx = tid + (i << 7);
                int sl = idx >> 3, q = idx & 7;
                ((float4*)xs)[idx] =
                    *(const float4*)(X + xbase + (size_t)(s0 + sl) * DM + dbase + (q << 2));
            }
        }
        __syncthreads();

        bool writey = (s0 >= s_out0);
        if (writey)
            scan_chunk<true>(us, xs, ys, h, A0, C0, lp, dloc);
        else
            scan_chunk<false>(us, xs, ys, h, A0, C0, lp, dloc);

        if (writey) {
            __syncthreads();
            // dump y chunk (coalesced) into d_out's y region
#pragma unroll
            for (int i = 0; i < 4; i++) {
                int idx = tid + (i << 7);
                int sl = idx >> 3, q = idx & 7;
                *(float4*)(Y + ((size_t)b * SEQ + s0 + sl) * DM + dbase + (q << 2)) =
                    ((float4*)ys)[idx];
            }
        }
    }

    if (Hout && c == NCHUNK - 1) {   // h_final [B, D, N], lane lp owns n = lp + 4j
#pragma unroll
        for (int j = 0; j < 16; j++)
            Hout[(((size_t)b * DM + d) << 6) + lp + (j << 2)] = h[j];
    }
}

// ---------------- kernel 4: normalize + residual + clip (in place) -------
__global__ void __launch_bounds__(256) finalize_kernel(const float* __restrict__ X,
                                                       float* __restrict__ out) {
    size_t row = blockIdx.x;   // b*SEQ + s
    int tid = threadIdx.x;
    float4 v = ((const float4*)(out + row * DM))[tid];
    float ps = v.x + v.y + v.z + v.w;
#pragma unroll
    for (int o = 16; o; o >>= 1) ps += __shfl_xor_sync(0xffffffffu, ps, o);
    __shared__ float wsum[8];
    if ((tid & 31) == 0) wsum[tid >> 5] = ps;
    __syncthreads();
    float tot = 0.0f;
#pragma unroll
    for (int w = 0; w < 8; w++) tot += wsum[w];
    float inv = 1.0f / (tot + 1e-6f);
    float4 xv = ((const float4*)(X + row * DM))[tid];
    float4 gv = ((const float4*)g_g)[tid];
    float4 r;
    r.x = __saturatef(fmaf(v.x * gv.x, inv, xv.x));
    r.y = __saturatef(fmaf(v.y * gv.y, inv, xv.y));
    r.z = __saturatef(fmaf(v.z * gv.z, inv, xv.z));
    r.w = __saturatef(fmaf(v.w * gv.w, inv, xv.w));
    ((float4*)(out + row * DM))[tid] = r;
}

// ---------------- launch ----------------
extern "C" void kernel_launch(void* const* d_in, const int* in_sizes, int n_in,
                              void* d_out, int out_size) {
    const float* x     = (const float*)d_in[0];
    const float* A_raw = (const float*)d_in[1];
    const float* B_w   = (const float*)d_in[2];
    const float* C_w   = (const float*)d_in[3];
    const float* gamma = (const float*)d_in[4];
    float* out = (float*)d_out;

    const size_t Y_ELEMS = (size_t)BB * SEQ * DM;       // 33,554,432
    const size_t H_ELEMS = (size_t)BB * DM * NS;        // 524,288
    float* hout = ((size_t)out_size >= Y_ELEMS + H_ELEMS) ? (out + Y_ELEMS) : nullptr;

    prep_kernel<<<256, 256>>>(A_raw, B_w, C_w, gamma);
    gemm_kernel<<<(BB * SEQ) / 64, 256>>>(x);
    scan_kernel<<<dim3(DM / 32, NCHUNK, BB), 128>>>(x, out, hout);
    finalize_kernel<<<BB * SEQ, 256>>>(x, out);
}

// round 8
// speedup vs baseline: 1.1673x; 1.0060x over previous
#include <cuda_runtime.h>
#include <math.h>

#define BB 8
#define SEQ 4096
#define DM 1024
#define NS 64
#define SCH 64          // scan steps per smem chunk
#define CHUNK 512       // sequence chunk per CTA (parallel-in-time)
#define WARM 64         // warmup steps (state error <= 0.7311^64 ~ 2e-9)
#define NCHUNK (SEQ / CHUNK)

typedef unsigned long long u64;

// ---------------- static scratch (no allocations allowed) ----------------
__device__ __align__(16) float g_Bs[NS * DM];              // sigmoid(B_w), [N, D]
__device__ __align__(16) float g_Aperm[DM * NS];           // sigmoid(A_raw), permuted n
__device__ __align__(16) float g_Cperm[DM * NS];           // sigmoid(C_w), permuted n
__device__ __align__(16) float g_g[DM];                    // sigmoid(gamma)
__device__ __align__(16) float g_U[(size_t)BB * SEQ * NS]; // X @ Bm^T, permuted n

__device__ __forceinline__ float sigmoidf_(float v) {
    return 1.0f / (1.0f + expf(-v));
}

// ---------------- packed f32x2 helpers ----------------
__device__ __forceinline__ u64 pack2(float lo, float hi) {
    u64 r;
    asm("mov.b64 %0, {%1, %2};" : "=l"(r) : "f"(lo), "f"(hi));
    return r;
}
__device__ __forceinline__ void unpack2(u64 v, float& lo, float& hi) {
    asm("mov.b64 {%0, %1}, %2;" : "=f"(lo), "=f"(hi) : "l"(v));
}
__device__ __forceinline__ u64 fma2_(u64 a, u64 b, u64 c) {
    u64 r;
    asm("fma.rn.f32x2 %0, %1, %2, %3;" : "=l"(r) : "l"(a), "l"(b), "l"(c));
    return r;
}

// State update for one pair of states:
//   t = u2 * (xv,xv);  h = h*A + t  (packed);  h = min(h, 1) (scalar, ALU pipe)
// Lower clip is provably never active: u>=0, x>=0, A>0, h0=0 => h*A+u*x >= 0.
__device__ __forceinline__ void step_pair(float& h0, float& h1, u64 u2, u64 xp, u64 a2) {
    asm("{\n\t"
        ".reg .b64 t, hp;\n\t"
        "mul.rn.f32x2 t, %2, %3;\n\t"
        "mov.b64 hp, {%0, %1};\n\t"
        "fma.rn.f32x2 hp, hp, %4, t;\n\t"
        "mov.b64 {%0, %1}, hp;\n\t"
        "}\n\t"
        : "+f"(h0), "+f"(h1) : "l"(u2), "l"(xp), "l"(a2));
    h0 = fminf(h0, 1.0f);
    h1 = fminf(h1, 1.0f);
}

__device__ __forceinline__ void dot_pair(u64& p2, float h0, float h1, u64 c2) {
    asm("{\n\t"
        ".reg .b64 hp;\n\t"
        "mov.b64 hp, {%1, %2};\n\t"
        "fma.rn.f32x2 %0, hp, %3, %0;\n\t"
        "}\n\t"
        : "+l"(p2) : "f"(h0), "f"(h1), "l"(c2));
}

// permutation: state n -> storage position, lane lp=n%4 owns n = lp + 4j,
// stored at lp*16 + j so each lane reads 16 contiguous floats (4x LDS.128)
__device__ __forceinline__ int permn(int n) { return ((n & 3) << 4) | (n >> 2); }

// ---------------- kernel 1: precompute sigmoids ----------------
__global__ void prep_kernel(const float* __restrict__ A_raw,
                            const float* __restrict__ B_w,
                            const float* __restrict__ C_w,
                            const float* __restrict__ gamma) {
    int i = blockIdx.x * 256 + threadIdx.x;
    if (i < NS * DM) {
        g_Bs[i] = sigmoidf_(B_w[i]);           // B_w is [N, D]
        int d = i >> 6, n = i & 63;            // A_raw / C_w are [D, N]
        int p = permn(n);
        g_Aperm[(d << 6) + p] = sigmoidf_(A_raw[i]);
        g_Cperm[(d << 6) + p] = sigmoidf_(C_w[i]);
    }
    if (i < DM) g_g[i] = sigmoidf_(gamma[i]);
}

// ---------------- kernel 2: U = X @ Bs^T  ([32768,1024] x [64,1024]^T) ----
__global__ void __launch_bounds__(256) gemm_kernel(const float* __restrict__ X) {
    __shared__ __align__(16) float Xs[32][68];  // k-major, padded (row = 272B, 16B-aligned)
    __shared__ __align__(16) float Ws[32][68];
    int tid = threadIdx.x;
    int row0 = blockIdx.x * 64;
    int tx = tid & 15, ty = tid >> 4;
    u64 acc2[4][2];
#pragma unroll
    for (int i = 0; i < 4; i++) { acc2[i][0] = 0ull; acc2[i][1] = 0ull; }

    for (int k0 = 0; k0 < DM; k0 += 32) {
        __syncthreads();
#pragma unroll
        for (int i = tid; i < 512; i += 256) {
            int r = i >> 3, q = i & 7;
            float4 v = *(const float4*)(X + (size_t)(row0 + r) * DM + k0 + q * 4);
            Xs[q * 4 + 0][r] = v.x; Xs[q * 4 + 1][r] = v.y;
            Xs[q * 4 + 2][r] = v.z; Xs[q * 4 + 3][r] = v.w;
            float4 w = *(const float4*)(g_Bs + (size_t)r * DM + k0 + q * 4);
            Ws[q * 4 + 0][r] = w.x; Ws[q * 4 + 1][r] = w.y;
            Ws[q * 4 + 2][r] = w.z; Ws[q * 4 + 3][r] = w.w;
        }
        __syncthreads();
#pragma unroll
        for (int k = 0; k < 32; k++) {
            float4 xa = *(const float4*)&Xs[k][ty * 4];
            ulonglong2 wv = *(const ulonglong2*)&Ws[k][tx * 4];  // (w0,w1),(w2,w3) packed
            u64 xp[4] = {pack2(xa.x, xa.x), pack2(xa.y, xa.y),
                         pack2(xa.z, xa.z), pack2(xa.w, xa.w)};
#pragma unroll
            for (int i = 0; i < 4; i++) {
                acc2[i][0] = fma2_(xp[i], wv.x, acc2[i][0]);
                acc2[i][1] = fma2_(xp[i], wv.y, acc2[i][1]);
            }
        }
    }
#pragma unroll
    for (int i = 0; i < 4; i++) {
        float a0, a1, a2, a3;
        unpack2(acc2[i][0], a0, a1);
        unpack2(acc2[i][1], a2, a3);
        size_t rb = (size_t)(row0 + ty * 4 + i) * NS;
        g_U[rb + permn(tx * 4 + 0)] = a0;
        g_U[rb + permn(tx * 4 + 1)] = a1;
        g_U[rb + permn(tx * 4 + 2)] = a2;
        g_U[rb + permn(tx * 4 + 3)] = a3;
    }
}

// ---------------- kernel 3: chunked parallel scan ----------------
// grid (D/32, NCHUNK, B), block 128. Warp owns 8 d's (4 lanes each),
// lane owns 16 n-states (8 f32x2 pairs). Chunks overlap 64 warmup steps
// (contraction factor <= sigmoid(1)^64 ~ 2e-9 kills initial-state error).

template <bool WRITE_Y>
__device__ __forceinline__ void scan_chunk(
    const float* __restrict__ us, const float* __restrict__ xs,
    float* __restrict__ ys, float* h, const u64* A2, const u64* C2,
    int lp, int dloc) {
#pragma unroll 2
    for (int sl = 0; sl < SCH; ++sl) {
        const ulonglong2* up = (const ulonglong2*)(us + (sl << 6) + (lp << 4));
        ulonglong2 ua = up[0], ub = up[1], uc = up[2], ud = up[3];
        float xv = xs[(sl << 5) + dloc];
        u64 xp = pack2(xv, xv);
        step_pair(h[0],  h[1],  ua.x, xp, A2[0]);
        step_pair(h[2],  h[3],  ua.y, xp, A2[1]);
        step_pair(h[4],  h[5],  ub.x, xp, A2[2]);
        step_pair(h[6],  h[7],  ub.y, xp, A2[3]);
        step_pair(h[8],  h[9],  uc.x, xp, A2[4]);
        step_pair(h[10], h[11], uc.y, xp, A2[5]);
        step_pair(h[12], h[13], ud.x, xp, A2[6]);
        step_pair(h[14], h[15], ud.y, xp, A2[7]);
        if (WRITE_Y) {
            u64 p2 = 0ull;
#pragma unroll
            for (int j = 0; j < 8; j++) dot_pair(p2, h[2 * j], h[2 * j + 1], C2[j]);
            float plo, phi;
            unpack2(p2, plo, phi);
            float p = plo + phi;
            p += __shfl_xor_sync(0xffffffffu, p, 1, 4);
            p += __shfl_xor_sync(0xffffffffu, p, 2, 4);
            if (lp == 0) ys[(sl << 5) + dloc] = p;
        }
    }
}

__global__ void __launch_bounds__(128) scan_kernel(const float* __restrict__ X,
                                                   float* __restrict__ Y,
                                                   float* __restrict__ Hout) {
    __shared__ __align__(16) float us[SCH * 64];   // u chunk, permuted-n layout
    __shared__ __align__(16) float xs[SCH * 32];   // x chunk for this CTA's 32 d
    __shared__ __align__(16) float ys[SCH * 32];   // y chunk (pre-normalization)

    int b = blockIdx.z;
    int c = blockIdx.y;
    int dbase = blockIdx.x << 5;
    int tid = threadIdx.x;
    int warp = tid >> 5, lane = tid & 31;
    int grp = lane >> 2, lp = lane & 3;
    int dloc = (warp << 3) | grp;    // 0..31
    int d = dbase + dloc;

    u64 A2[8], C2[8];
    float h[16];
#pragma unroll
    for (int q = 0; q < 4; q++) {
        ulonglong2 a = ((const ulonglong2*)(g_Aperm + ((size_t)d << 6) + (lp << 4)))[q];
        A2[q * 2 + 0] = a.x; A2[q * 2 + 1] = a.y;
        ulonglong2 cc = ((const ulonglong2*)(g_Cperm + ((size_t)d << 6) + (lp << 4)))[q];
        C2[q * 2 + 0] = cc.x; C2[q * 2 + 1] = cc.y;
    }
#pragma unroll
    for (int j = 0; j < 16; j++) h[j] = 0.0f;

    const size_t xbase = (size_t)b * SEQ * DM;
    const int s_out0 = c * CHUNK;
    const int s_begin = (c == 0) ? 0 : s_out0 - WARM;
    const int s_end = s_out0 + CHUNK;

    for (int s0 = s_begin; s0 < s_end; s0 += SCH) {
        __syncthreads();
        {   // stage u chunk (coalesced, contiguous): 64 steps x 64 floats
            const float4* src = (const float4*)(g_U + ((size_t)b * SEQ + s0) * NS);
            float4* dst = (float4*)us;
#pragma unroll
            for (int i = 0; i < 8; i++) dst[tid + (i << 7)] = src[tid + (i << 7)];
            // stage x chunk: 64 steps x 32 d
#pragma unroll
            for (int i = 0; i < 4; i++) {
                int idx = tid + (i << 7);
                int sl = idx >> 3, q = idx & 7;
                ((float4*)xs)[idx] =
                    *(const float4*)(X + xbase + (size_t)(s0 + sl) * DM + dbase + (q << 2));
            }
        }
        __syncthreads();

        bool writey = (s0 >= s_out0);
        if (writey)
            scan_chunk<true>(us, xs, ys, h, A2, C2, lp, dloc);
        else
            scan_chunk<false>(us, xs, ys, h, A2, C2, lp, dloc);

        if (writey) {
            __syncthreads();
            // dump y chunk (coalesced) into d_out's y region
#pragma unroll
            for (int i = 0; i < 4; i++) {
                int idx = tid + (i << 7);
                int sl = idx >> 3, q = idx & 7;
                *(float4*)(Y + ((size_t)b * SEQ + s0 + sl) * DM + dbase + (q << 2)) =
                    ((float4*)ys)[idx];
            }
        }
    }

    if (Hout && c == NCHUNK - 1) {   // h_final [B, D, N], lane lp owns n = lp + 4j
#pragma unroll
        for (int j = 0; j < 16; j++)
            Hout[(((size_t)b * DM + d) << 6) + lp + (j << 2)] = h[j];
    }
}

// ---------------- kernel 4: normalize + residual + clip (in place) -------
__global__ void __launch_bounds__(256) finalize_kernel(const float* __restrict__ X,
                                                       float* __restrict__ out) {
    size_t row = blockIdx.x;   // b*SEQ + s
    int tid = threadIdx.x;
    float4 v = ((const float4*)(out + row * DM))[tid];
    float ps = v.x + v.y + v.z + v.w;
#pragma unroll
    for (int o = 16; o; o >>= 1) ps += __shfl_xor_sync(0xffffffffu, ps, o);
    __shared__ float wsum[8];
    if ((tid & 31) == 0) wsum[tid >> 5] = ps;
    __syncthreads();
    float tot = 0.0f;
#pragma unroll
    for (int w = 0; w < 8; w++) tot += wsum[w];
    float inv = 1.0f / (tot + 1e-6f);
    float4 xv = ((const float4*)(X + row * DM))[tid];
    float4 gv = ((const float4*)g_g)[tid];
    float4 r;
    r.x = __saturatef(fmaf(v.x * gv.x, inv, xv.x));
    r.y = __saturatef(fmaf(v.y * gv.y, inv, xv.y));
    r.z = __saturatef(fmaf(v.z * gv.z, inv, xv.z));
    r.w = __saturatef(fmaf(v.w * gv.w, inv, xv.w));
    ((float4*)(out + row * DM))[tid] = r;
}

// ---------------- launch ----------------
extern "C" void kernel_launch(void* const* d_in, const int* in_sizes, int n_in,
                              void* d_out, int out_size) {
    const float* x     = (const float*)d_in[0];
    const float* A_raw = (const float*)d_in[1];
    const float* B_w   = (const float*)d_in[2];
    const float* C_w   = (const float*)d_in[3];
    const float* gamma = (const float*)d_in[4];
    float* out = (float*)d_out;

    const size_t Y_ELEMS = (size_t)BB * SEQ * DM;       // 33,554,432
    const size_t H_ELEMS = (size_t)BB * DM * NS;        // 524,288
    float* hout = ((size_t)out_size >= Y_ELEMS + H_ELEMS) ? (out + Y_ELEMS) : nullptr;

    prep_kernel<<<256, 256>>>(A_raw, B_w, C_w, gamma);
    gemm_kernel<<<(BB * SEQ) / 64, 256>>>(x);
    scan_kernel<<<dim3(DM / 32, NCHUNK, BB), 128>>>(x, out, hout);
    finalize_kernel<<<BB * SEQ, 256>>>(x, out);
}

// round 9
// speedup vs baseline: 2.5443x; 2.1796x over previous
#include <cuda_runtime.h>
#include <math.h>

#define BB 8
#define SEQ 4096
#define DM 1024
#define NS 64
#define SCH 64          // scan steps per smem chunk
#define CHUNK 512       // sequence chunk per CTA (parallel-in-time)
#define WARM 64         // warmup steps (state error <= 0.7311^64 ~ 2e-9)
#define NCHUNK (SEQ / CHUNK)

typedef unsigned long long u64;

// ---------------- static scratch (no allocations allowed) ----------------
__device__ __align__(16) float g_Bs[NS * DM];              // sigmoid(B_w), [N, D]
__device__ __align__(16) float g_Aperm[DM * NS];           // sigmoid(A_raw), permuted n
__device__ __align__(16) float g_Cperm[DM * NS];           // sigmoid(C_w), permuted n
__device__ __align__(16) float g_g[DM];                    // sigmoid(gamma)
__device__ __align__(16) float g_sumC[DM];                 // sum_n sigmoid(C_w[d,n])
__device__ __align__(16) float g_U[(size_t)BB * SEQ * NS]; // X @ Bm^T, permuted n
__device__ __align__(16) float g_umin[(size_t)BB * SEQ];   // min_n U[b,s,n]

__device__ __forceinline__ float sigmoidf_(float v) {
    return 1.0f / (1.0f + expf(-v));
}

// ---------------- packed f32x2 helpers ----------------
__device__ __forceinline__ u64 pack2(float lo, float hi) {
    u64 r;
    asm("mov.b64 %0, {%1, %2};" : "=l"(r) : "f"(lo), "f"(hi));
    return r;
}
__device__ __forceinline__ void unpack2(u64 v, float& lo, float& hi) {
    asm("mov.b64 {%0, %1}, %2;" : "=f"(lo), "=f"(hi) : "l"(v));
}
__device__ __forceinline__ u64 fma2_(u64 a, u64 b, u64 c) {
    u64 r;
    asm("fma.rn.f32x2 %0, %1, %2, %3;" : "=l"(r) : "l"(a), "l"(b), "l"(c));
    return r;
}

// State update for one pair of states:
//   t = u2 * (xv,xv);  h = h*A + t  (packed);  h = min(h, 1) (scalar, ALU pipe)
// Lower clip is provably never active: u>=0, x>=0, A>0, h0=0 => h*A+u*x >= 0.
__device__ __forceinline__ void step_pair(float& h0, float& h1, u64 u2, u64 xp, u64 a2) {
    asm("{\n\t"
        ".reg .b64 t, hp;\n\t"
        "mul.rn.f32x2 t, %2, %3;\n\t"
        "mov.b64 hp, {%0, %1};\n\t"
        "fma.rn.f32x2 hp, hp, %4, t;\n\t"
        "mov.b64 {%0, %1}, hp;\n\t"
        "}\n\t"
        : "+f"(h0), "+f"(h1) : "l"(u2), "l"(xp), "l"(a2));
    h0 = fminf(h0, 1.0f);
    h1 = fminf(h1, 1.0f);
}

__device__ __forceinline__ void dot_pair(u64& p2, float h0, float h1, u64 c2) {
    asm("{\n\t"
        ".reg .b64 hp;\n\t"
        "mov.b64 hp, {%1, %2};\n\t"
        "fma.rn.f32x2 %0, hp, %3, %0;\n\t"
        "}\n\t"
        : "+l"(p2) : "f"(h0), "f"(h1), "l"(c2));
}

// permutation: state n -> storage position, lane lp=n%4 owns n = lp + 4j,
// stored at lp*16 + j so each lane reads 16 contiguous floats (4x LDS/LDG.128)
__device__ __forceinline__ int permn(int n) { return ((n & 3) << 4) | (n >> 2); }

// ---------------- kernel 1: precompute sigmoids ----------------
__global__ void prep_kernel(const float* __restrict__ A_raw,
                            const float* __restrict__ B_w,
                            const float* __restrict__ C_w,
                            const float* __restrict__ gamma) {
    int i = blockIdx.x * 256 + threadIdx.x;
    if (i < NS * DM) {
        g_Bs[i] = sigmoidf_(B_w[i]);           // B_w is [N, D]
        int d = i >> 6, n = i & 63;            // A_raw / C_w are [D, N]
        int p = permn(n);
        g_Aperm[(d << 6) + p] = sigmoidf_(A_raw[i]);
        g_Cperm[(d << 6) + p] = sigmoidf_(C_w[i]);
    }
    if (i < DM) {
        g_g[i] = sigmoidf_(gamma[i]);
        float s = 0.0f;
        for (int n = 0; n < NS; n++) s += sigmoidf_(C_w[i * NS + n]);
        g_sumC[i] = s;    // y_d when all 64 states saturate at 1.0
    }
}

// ---------------- kernel 2: U = X @ Bs^T  ([32768,1024] x [64,1024]^T) ----
__global__ void __launch_bounds__(256) gemm_kernel(const float* __restrict__ X) {
    __shared__ __align__(16) float Xs[32][68];  // k-major, padded
    __shared__ __align__(16) float Ws[32][68];
    int tid = threadIdx.x;
    int row0 = blockIdx.x * 64;
    int tx = tid & 15, ty = tid >> 4;
    u64 acc2[4][2];
#pragma unroll
    for (int i = 0; i < 4; i++) { acc2[i][0] = 0ull; acc2[i][1] = 0ull; }

    for (int k0 = 0; k0 < DM; k0 += 32) {
        __syncthreads();
#pragma unroll
        for (int i = tid; i < 512; i += 256) {
            int r = i >> 3, q = i & 7;
            float4 v = *(const float4*)(X + (size_t)(row0 + r) * DM + k0 + q * 4);
            Xs[q * 4 + 0][r] = v.x; Xs[q * 4 + 1][r] = v.y;
            Xs[q * 4 + 2][r] = v.z; Xs[q * 4 + 3][r] = v.w;
            float4 w = *(const float4*)(g_Bs + (size_t)r * DM + k0 + q * 4);
            Ws[q * 4 + 0][r] = w.x; Ws[q * 4 + 1][r] = w.y;
            Ws[q * 4 + 2][r] = w.z; Ws[q * 4 + 3][r] = w.w;
        }
        __syncthreads();
#pragma unroll
        for (int k = 0; k < 32; k++) {
            float4 xa = *(const float4*)&Xs[k][ty * 4];
            ulonglong2 wv = *(const ulonglong2*)&Ws[k][tx * 4];
            u64 xp[4] = {pack2(xa.x, xa.x), pack2(xa.y, xa.y),
                         pack2(xa.z, xa.z), pack2(xa.w, xa.w)};
#pragma unroll
            for (int i = 0; i < 4; i++) {
                acc2[i][0] = fma2_(xp[i], wv.x, acc2[i][0]);
                acc2[i][1] = fma2_(xp[i], wv.y, acc2[i][1]);
            }
        }
    }
#pragma unroll
    for (int i = 0; i < 4; i++) {
        float a0, a1, a2, a3;
        unpack2(acc2[i][0], a0, a1);
        unpack2(acc2[i][1], a2, a3);
        size_t rb = (size_t)(row0 + ty * 4 + i) * NS;
        g_U[rb + permn(tx * 4 + 0)] = a0;
        g_U[rb + permn(tx * 4 + 1)] = a1;
        g_U[rb + permn(tx * 4 + 2)] = a2;
        g_U[rb + permn(tx * 4 + 3)] = a3;
    }
}

// ---------------- kernel 2b: umin[b,s] = min_n U[b,s,n] ----------------
// 8 lanes per row (row = b*SEQ+s), each loads 8 floats. grid = BB*SEQ*8/256.
__global__ void __launch_bounds__(256) umin_kernel() {
    int gid = blockIdx.x * 256 + threadIdx.x;
    int row = gid >> 3, l = gid & 7;
    const float4* U4 = (const float4*)g_U;
    float4 v1 = U4[(size_t)row * 16 + l * 2];
    float4 v2 = U4[(size_t)row * 16 + l * 2 + 1];
    float m = fminf(fminf(fminf(v1.x, v1.y), fminf(v1.z, v1.w)),
                    fminf(fminf(v2.x, v2.y), fminf(v2.z, v2.w)));
    m = fminf(m, __shfl_xor_sync(0xffffffffu, m, 1, 8));
    m = fminf(m, __shfl_xor_sync(0xffffffffu, m, 2, 8));
    m = fminf(m, __shfl_xor_sync(0xffffffffu, m, 4, 8));
    if (l == 0) g_umin[row] = m;
}

// ---------------- kernel 3: chunked parallel scan, saturation fast path --
// grid (D/32, NCHUNK, B), block 128. Warp owns 8 d's (4 lanes each), lane
// owns 16 n-states. If x[b,s,d]*umin[b,s] >= 1 then EVERY state of that d
// saturates to exactly 1.0 this step (min(1, h*A + u*x) with u*x >= 1, RN
// monotone, h*A >= 0) and y_d = sum_n C[d,n]. Warp-vote: if all 8 d's
// saturate, skip the whole update. Slow path fetches u/A/C from L2.

template <bool WRITE_Y>
__device__ __forceinline__ void scan_chunk(
    int b, int s0, const float* __restrict__ xs, const float* __restrict__ ums,
    float* __restrict__ ys, float* h, bool& ones, float sumCd,
    int d, int lp, int dloc) {
#pragma unroll 4
    for (int sl = 0; sl < SCH; ++sl) {
        float xv = xs[(sl << 5) + dloc];
        float um = ums[sl];
        bool sat = (xv * um >= 1.0f);
        float yv = sumCd;
        if (!__all_sync(0xffffffffu, sat)) {
            // slow path (warp-uniform branch)
            if (ones) {
#pragma unroll
                for (int j = 0; j < 16; j++) h[j] = 1.0f;
                ones = false;
            }
            const ulonglong2* up = (const ulonglong2*)(
                g_U + (((size_t)b * SEQ + s0 + sl) << 6) + (lp << 4));
            ulonglong2 u0 = up[0], u1 = up[1], u2 = up[2], u3 = up[3];
            const ulonglong2* ap = (const ulonglong2*)(
                g_Aperm + ((size_t)d << 6) + (lp << 4));
            ulonglong2 a0 = ap[0], a1 = ap[1], a2 = ap[2], a3 = ap[3];
            u64 xp = pack2(xv, xv);
            step_pair(h[0],  h[1],  u0.x, xp, a0.x);
            step_pair(h[2],  h[3],  u0.y, xp, a0.y);
            step_pair(h[4],  h[5],  u1.x, xp, a1.x);
            step_pair(h[6],  h[7],  u1.y, xp, a1.y);
            step_pair(h[8],  h[9],  u2.x, xp, a2.x);
            step_pair(h[10], h[11], u2.y, xp, a2.y);
            step_pair(h[12], h[13], u3.x, xp, a3.x);
            step_pair(h[14], h[15], u3.y, xp, a3.y);
            if (WRITE_Y) {
                const ulonglong2* cp = (const ulonglong2*)(
                    g_Cperm + ((size_t)d << 6) + (lp << 4));
                ulonglong2 c0 = cp[0], c1 = cp[1], c2 = cp[2], c3 = cp[3];
                u64 p2 = 0ull;
                dot_pair(p2, h[0],  h[1],  c0.x);
                dot_pair(p2, h[2],  h[3],  c0.y);
                dot_pair(p2, h[4],  h[5],  c1.x);
                dot_pair(p2, h[6],  h[7],  c1.y);
                dot_pair(p2, h[8],  h[9],  c2.x);
                dot_pair(p2, h[10], h[11], c2.y);
                dot_pair(p2, h[12], h[13], c3.x);
                dot_pair(p2, h[14], h[15], c3.y);
                float plo, phi;
                unpack2(p2, plo, phi);
                float p = plo + phi;
                p += __shfl_xor_sync(0xffffffffu, p, 1, 4);
                p += __shfl_xor_sync(0xffffffffu, p, 2, 4);
                yv = p;
            }
        } else {
            ones = true;   // h == all-ones, materialized lazily
        }
        if (WRITE_Y && lp == 0) ys[(sl << 5) + dloc] = yv;
    }
}

__global__ void __launch_bounds__(128) scan_kernel(const float* __restrict__ X,
                                                   float* __restrict__ Y,
                                                   float* __restrict__ Hout) {
    __shared__ __align__(16) float xs[SCH * 32];   // x chunk for this CTA's 32 d
    __shared__ __align__(16) float ys[SCH * 32];   // y chunk (pre-normalization)
    __shared__ __align__(16) float ums[SCH];       // umin chunk

    int b = blockIdx.z;
    int c = blockIdx.y;
    int dbase = blockIdx.x << 5;
    int tid = threadIdx.x;
    int warp = tid >> 5, lane = tid & 31;
    int grp = lane >> 2, lp = lane & 3;
    int dloc = (warp << 3) | grp;    // 0..31
    int d = dbase + dloc;

    float h[16];
    bool ones = false;
#pragma unroll
    for (int j = 0; j < 16; j++) h[j] = 0.0f;
    float sumCd = g_sumC[d];

    const size_t xbase = (size_t)b * SEQ * DM;
    const int s_out0 = c * CHUNK;
    const int s_begin = (c == 0) ? 0 : s_out0 - WARM;
    const int s_end = s_out0 + CHUNK;

    for (int s0 = s_begin; s0 < s_end; s0 += SCH) {
        __syncthreads();
        {   // stage x chunk: 64 steps x 32 d (coalesced)
#pragma unroll
            for (int i = 0; i < 4; i++) {
                int idx = tid + (i << 7);
                int sl = idx >> 3, q = idx & 7;
                ((float4*)xs)[idx] =
                    *(const float4*)(X + xbase + (size_t)(s0 + sl) * DM + dbase + (q << 2));
            }
            if (tid < 16)
                ((float4*)ums)[tid] =
                    ((const float4*)(g_umin + (size_t)b * SEQ + s0))[tid];
        }
        __syncthreads();

        bool writey = (s0 >= s_out0);
        if (writey)
            scan_chunk<true>(b, s0, xs, ums, ys, h, ones, sumCd, d, lp, dloc);
        else
            scan_chunk<false>(b, s0, xs, ums, ys, h, ones, sumCd, d, lp, dloc);

        if (writey) {
            __syncthreads();
            // dump y chunk (coalesced) into d_out's y region
#pragma unroll
            for (int i = 0; i < 4; i++) {
                int idx = tid + (i << 7);
                int sl = idx >> 3, q = idx & 7;
                *(float4*)(Y + ((size_t)b * SEQ + s0 + sl) * DM + dbase + (q << 2)) =
                    ((float4*)ys)[idx];
            }
        }
    }

    if (Hout && c == NCHUNK - 1) {   // h_final [B, D, N], lane lp owns n = lp + 4j
#pragma unroll
        for (int j = 0; j < 16; j++) {
            float hv = ones ? 1.0f : h[j];
            Hout[(((size_t)b * DM + d) << 6) + lp + (j << 2)] = hv;
        }
    }
}

// ---------------- kernel 4: normalize + residual + clip (in place) -------
__global__ void __launch_bounds__(256) finalize_kernel(const float* __restrict__ X,
                                                       float* __restrict__ out) {
    size_t row = blockIdx.x;   // b*SEQ + s
    int tid = threadIdx.x;
    float4 v = ((const float4*)(out + row * DM))[tid];
    float ps = v.x + v.y + v.z + v.w;
#pragma unroll
    for (int o = 16; o; o >>= 1) ps += __shfl_xor_sync(0xffffffffu, ps, o);
    __shared__ float wsum[8];
    if ((tid & 31) == 0) wsum[tid >> 5] = ps;
    __syncthreads();
    float tot = 0.0f;
#pragma unroll
    for (int w = 0; w < 8; w++) tot += wsum[w];
    float inv = 1.0f / (tot + 1e-6f);
    float4 xv = ((const float4*)(X + row * DM))[tid];
    float4 gv = ((const float4*)g_g)[tid];
    float4 r;
    r.x = __saturatef(fmaf(v.x * gv.x, inv, xv.x));
    r.y = __saturatef(fmaf(v.y * gv.y, inv, xv.y));
    r.z = __saturatef(fmaf(v.z * gv.z, inv, xv.z));
    r.w = __saturatef(fmaf(v.w * gv.w, inv, xv.w));
    ((float4*)(out + row * DM))[tid] = r;
}

// ---------------- launch ----------------
extern "C" void kernel_launch(void* const* d_in, const int* in_sizes, int n_in,
                              void* d_out, int out_size) {
    const float* x     = (const float*)d_in[0];
    const float* A_raw = (const float*)d_in[1];
    const float* B_w   = (const float*)d_in[2];
    const float* C_w   = (const float*)d_in[3];
    const float* gamma = (const float*)d_in[4];
    float* out = (float*)d_out;

    const size_t Y_ELEMS = (size_t)BB * SEQ * DM;       // 33,554,432
    const size_t H_ELEMS = (size_t)BB * DM * NS;        // 524,288
    float* hout = ((size_t)out_size >= Y_ELEMS + H_ELEMS) ? (out + Y_ELEMS) : nullptr;

    prep_kernel<<<256, 256>>>(A_raw, B_w, C_w, gamma);
    gemm_kernel<<<(BB * SEQ) / 64, 256>>>(x);
    umin_kernel<<<(BB * SEQ * 8) / 256, 256>>>();
    scan_kernel<<<dim3(DM / 32, NCHUNK, BB), 128>>>(x, out, hout);
    finalize_kernel<<<BB * SEQ, 256>>>(x, out);
}